// round 5
// baseline (speedup 1.0000x reference)
#include <cuda_runtime.h>
#include <math.h>

#define N_NODES 100000
#define N_EDGES 1600000
#define IN_DIM 128
#define HID 64
#define NTILES ((N_NODES + 255) / 256)   // 391

// ---------------- scratch (__device__ globals; referenced from DEVICE code only) ----------------
__device__ int d_is64;                         // 1 if edge_index delivered as int64
__device__ __align__(16) int d_src[N_EDGES];   // canonical int32 src
__device__ __align__(16) int d_dst[N_EDGES];   // canonical int32 dst
__device__ __align__(16) int d_cnt[N_NODES];
__device__ __align__(16) int d_rowptr[N_NODES + 1];
__device__ __align__(16) int d_bsum[512];
__device__ __align__(16) int d_boff[512];
__device__ __align__(16) int d_eidx[N_EDGES];
__device__ __align__(16) float d_dinv[N_NODES];
__device__ __align__(16) float d_g1[(size_t)N_NODES * HID];   // (x@W1)*dinv
__device__ __align__(16) float d_h1[(size_t)N_NODES * HID];   // relu(dinv*agg + b1)
__device__ __align__(16) float d_g2[(size_t)N_NODES * HID];   // (h1@W2)*dinv
__device__ __align__(16) float d_emb[(size_t)N_NODES * HID];  // dinv*agg + b2

// ---------------- dtype detection ----------------
// int64 edge_index (values < 2^31): every odd 32-bit word is 0. int32: odd words random.
__global__ void detect_kernel(const int* __restrict__ ei32) {
    __shared__ int any_nonzero;
    if (threadIdx.x == 0) any_nonzero = 0;
    __syncthreads();
    int local = 0;
    for (int i = threadIdx.x; i < 2048; i += blockDim.x)
        local |= ei32[2 * i + 1];
    if (local) atomicOr(&any_nonzero, 1);
    __syncthreads();
    if (threadIdx.x == 0) d_is64 = (any_nonzero == 0) ? 1 : 0;
}

__global__ void zero_cnt_kernel() {
    int i = blockIdx.x * blockDim.x + threadIdx.x;
    if (i < N_NODES) d_cnt[i] = 0;
}

// convert to canonical int32 + in-degree histogram, one pass
__global__ void convert_hist_kernel(const int* __restrict__ ei32) {
    int e = blockIdx.x * blockDim.x + threadIdx.x;
    if (e >= N_EDGES) return;
    int s, d;
    if (d_is64) {               // little-endian int64: low word holds the value
        s = ei32[2 * e];
        d = ei32[2 * (N_EDGES + e)];
    } else {
        s = ei32[e];
        d = ei32[N_EDGES + e];
    }
    s = min(max(s, 0), N_NODES - 1);   // clamp: no wild addresses downstream
    d = min(max(d, 0), N_NODES - 1);
    d_src[e] = s;
    d_dst[e] = d;
    atomicAdd(&d_cnt[d], 1);
}

// per-256-tile inclusive scan of degrees; also computes dinv and re-zeroes d_cnt for fill
__global__ void scanA_kernel() {
    __shared__ int s[256];
    int t = threadIdx.x;
    int i = blockIdx.x * 256 + t;
    int v = (i < N_NODES) ? d_cnt[i] : 0;
    if (i < N_NODES) {
        d_dinv[i] = rsqrtf((float)v + 1.0f);  // +1 self-loop
        d_cnt[i] = 0;                          // reset for fill's atomic cursor
    }
    s[t] = v;
    __syncthreads();
#pragma unroll
    for (int off = 1; off < 256; off <<= 1) {
        int a = (t >= off) ? s[t - off] : 0;
        __syncthreads();
        s[t] += a;
        __syncthreads();
    }
    if (i < N_NODES) d_rowptr[i + 1] = s[t];
    if (t == 255) d_bsum[blockIdx.x] = s[255];
}

// single-block exclusive scan of tile totals
__global__ void scanB_kernel() {
    __shared__ int s[512];
    int t = threadIdx.x;
    int v = (t < NTILES) ? d_bsum[t] : 0;
    s[t] = v;
    __syncthreads();
#pragma unroll
    for (int off = 1; off < 512; off <<= 1) {
        int a = (t >= off) ? s[t - off] : 0;
        __syncthreads();
        s[t] += a;
        __syncthreads();
    }
    d_boff[t] = s[t] - v;  // exclusive
}

__global__ void scanC_kernel() {
    int i = blockIdx.x * 256 + threadIdx.x;
    if (i < N_NODES) d_rowptr[i + 1] += d_boff[blockIdx.x];
    if (i == 0) d_rowptr[0] = 0;
}

__global__ void fill_kernel() {
    int e = blockIdx.x * blockDim.x + threadIdx.x;
    if (e >= N_EDGES) return;
    int d = d_dst[e];
    int pos = d_rowptr[d] + atomicAdd(&d_cnt[d], 1);
    d_eidx[pos] = d_src[e];
}

// ---------------- GEMM: out = (in @ W) * dinv  (128x64 tile, 256 thr, 8x4 micro) ----------------
// LAYER 0: in = x (param), out = d_g1.  LAYER 1: in = d_h1, out = d_g2.
template <int KDIM, int LAYER>
__global__ __launch_bounds__(256) void gemm_kernel(const float* __restrict__ xin,
                                                   const float* __restrict__ W) {
    const float* in = (LAYER == 0) ? xin : d_h1;
    float* out = (LAYER == 0) ? d_g1 : d_g2;

    __shared__ float sX[128 * 64];   // 32 KB
    __shared__ float sW[64 * 64];    // 16 KB
    int tid = threadIdx.x;
    int r0 = blockIdx.x * 128;
    int jg = tid & 15;   // 16 col groups x 4 cols
    int rg = tid >> 4;   // 16 row groups; rows rg + 16*{0..7}

    float acc[8][4];
#pragma unroll
    for (int a = 0; a < 8; a++)
#pragma unroll
        for (int b = 0; b < 4; b++) acc[a][b] = 0.0f;

#pragma unroll
    for (int kp = 0; kp < KDIM / 64; kp++) {
        for (int i = tid; i < 4096; i += 256) sW[i] = W[kp * 4096 + i];
#pragma unroll
        for (int it = 0; it < 8; it++) {
            int r = rg + 16 * it;
            int row = r0 + r;
            float4 v = make_float4(0.f, 0.f, 0.f, 0.f);
            if (row < N_NODES)
                v = *(const float4*)(in + (size_t)row * KDIM + kp * 64 + jg * 4);
            *(float4*)(sX + r * 64 + jg * 4) = v;
        }
        __syncthreads();
#pragma unroll 4
        for (int k = 0; k < 64; k++) {
            float4 w4 = *(const float4*)(sW + k * 64 + jg * 4);
#pragma unroll
            for (int it = 0; it < 8; it++) {
                float xv = sX[(rg + 16 * it) * 64 + k];
                acc[it][0] = fmaf(xv, w4.x, acc[it][0]);
                acc[it][1] = fmaf(xv, w4.y, acc[it][1]);
                acc[it][2] = fmaf(xv, w4.z, acc[it][2]);
                acc[it][3] = fmaf(xv, w4.w, acc[it][3]);
            }
        }
        __syncthreads();
    }
#pragma unroll
    for (int it = 0; it < 8; it++) {
        int row = r0 + rg + 16 * it;
        if (row < N_NODES) {
            float dv = d_dinv[row];
            float4 o = make_float4(acc[it][0] * dv, acc[it][1] * dv,
                                   acc[it][2] * dv, acc[it][3] * dv);
            *(float4*)(out + (size_t)row * HID + jg * 4) = o;
        }
    }
}

// ---------------- gather-aggregate: out[n] = post(dinv[n]*(g[n] + sum g[src]) + bias) ----------
// 16 threads per node, each owns one float4 lane; 8-edge unroll for MLP.
template <int LAYER>
__global__ __launch_bounds__(256) void gather_kernel(const float* __restrict__ bias) {
    const float* g = (LAYER == 0) ? d_g1 : d_g2;
    float* out = (LAYER == 0) ? d_h1 : d_emb;

    int t = threadIdx.x;
    int node = blockIdx.x * 16 + (t >> 4);
    if (node >= N_NODES) return;
    int lane = t & 15;

    int base = d_rowptr[node];
    int end  = d_rowptr[node + 1];

    float4 a0 = *(const float4*)(g + (size_t)node * HID + lane * 4);  // self-loop
    float4 a1 = make_float4(0.f, 0.f, 0.f, 0.f);
    float4 a2 = make_float4(0.f, 0.f, 0.f, 0.f);
    float4 a3 = make_float4(0.f, 0.f, 0.f, 0.f);

    int i = base;
    for (; i + 8 <= end; i += 8) {
        int s0 = d_eidx[i + 0];
        int s1 = d_eidx[i + 1];
        int s2 = d_eidx[i + 2];
        int s3 = d_eidx[i + 3];
        int s4 = d_eidx[i + 4];
        int s5 = d_eidx[i + 5];
        int s6 = d_eidx[i + 6];
        int s7 = d_eidx[i + 7];
        float4 v0 = *(const float4*)(g + (size_t)s0 * HID + lane * 4);
        float4 v1 = *(const float4*)(g + (size_t)s1 * HID + lane * 4);
        float4 v2 = *(const float4*)(g + (size_t)s2 * HID + lane * 4);
        float4 v3 = *(const float4*)(g + (size_t)s3 * HID + lane * 4);
        float4 v4 = *(const float4*)(g + (size_t)s4 * HID + lane * 4);
        float4 v5 = *(const float4*)(g + (size_t)s5 * HID + lane * 4);
        float4 v6 = *(const float4*)(g + (size_t)s6 * HID + lane * 4);
        float4 v7 = *(const float4*)(g + (size_t)s7 * HID + lane * 4);
        a0.x += v0.x; a0.y += v0.y; a0.z += v0.z; a0.w += v0.w;
        a1.x += v1.x; a1.y += v1.y; a1.z += v1.z; a1.w += v1.w;
        a2.x += v2.x; a2.y += v2.y; a2.z += v2.z; a2.w += v2.w;
        a3.x += v3.x; a3.y += v3.y; a3.z += v3.z; a3.w += v3.w;
        a0.x += v4.x; a0.y += v4.y; a0.z += v4.z; a0.w += v4.w;
        a1.x += v5.x; a1.y += v5.y; a1.z += v5.z; a1.w += v5.w;
        a2.x += v6.x; a2.y += v6.y; a2.z += v6.z; a2.w += v6.w;
        a3.x += v7.x; a3.y += v7.y; a3.z += v7.z; a3.w += v7.w;
    }
    for (; i < end; i++) {
        int s = d_eidx[i];
        float4 v = *(const float4*)(g + (size_t)s * HID + lane * 4);
        a0.x += v.x; a0.y += v.y; a0.z += v.z; a0.w += v.w;
    }
    float4 sum = make_float4(a0.x + a1.x + a2.x + a3.x,
                             a0.y + a1.y + a2.y + a3.y,
                             a0.z + a1.z + a2.z + a3.z,
                             a0.w + a1.w + a2.w + a3.w);
    float dv = d_dinv[node];
    float4 bb = *(const float4*)(bias + lane * 4);
    float4 o;
    o.x = fmaf(dv, sum.x, bb.x);
    o.y = fmaf(dv, sum.y, bb.y);
    o.z = fmaf(dv, sum.z, bb.z);
    o.w = fmaf(dv, sum.w, bb.w);
    if (LAYER == 0) {
        o.x = fmaxf(o.x, 0.f); o.y = fmaxf(o.y, 0.f);
        o.z = fmaxf(o.z, 0.f); o.w = fmaxf(o.w, 0.f);
    }
    *(float4*)(out + (size_t)node * HID + lane * 4) = o;
}

// ---------------- final: logits = emb@Wl + bl; log_softmax. one warp/node ----------------
__global__ __launch_bounds__(256) void final_kernel(const float* __restrict__ Wl,
                                                    const float* __restrict__ bl,
                                                    float* __restrict__ out) {
    __shared__ float sWl[64 * 40];
    __shared__ float sbl[40];
    __shared__ float semb[8][64];
    int tid = threadIdx.x;
    for (int i = tid; i < 64 * 40; i += 256) sWl[i] = Wl[i];
    if (tid < 40) sbl[tid] = bl[tid];
    __syncthreads();

    int w = tid >> 5, lane = tid & 31;
    int n = blockIdx.x * 8 + w;
    if (n >= N_NODES) return;

    float e0 = d_emb[(size_t)n * HID + lane];
    float e1 = d_emb[(size_t)n * HID + 32 + lane];
    semb[w][lane] = e0;
    semb[w][32 + lane] = e1;
    __syncwarp();

    float v0 = sbl[lane];
    float v1 = (lane < 8) ? sbl[32 + lane] : -INFINITY;
#pragma unroll 8
    for (int k = 0; k < 64; k++) {
        float ev = semb[w][k];
        v0 = fmaf(ev, sWl[k * 40 + lane], v0);
        if (lane < 8) v1 = fmaf(ev, sWl[k * 40 + 32 + lane], v1);
    }
    float m = fmaxf(v0, v1);
#pragma unroll
    for (int o = 16; o; o >>= 1) m = fmaxf(m, __shfl_xor_sync(0xffffffffu, m, o));
    float s = expf(v0 - m) + ((lane < 8) ? expf(v1 - m) : 0.0f);
#pragma unroll
    for (int o = 16; o; o >>= 1) s += __shfl_xor_sync(0xffffffffu, s, o);
    float lse = m + logf(s);

    out[(size_t)n * 40 + lane] = v0 - lse;
    if (lane < 8) out[(size_t)n * 40 + 32 + lane] = v1 - lse;
}

extern "C" void kernel_launch(void* const* d_in, const int* in_sizes, int n_in,
                              void* d_out, int out_size) {
    const float* x = (const float*)d_in[0];
    const int* ei32 = (const int*)d_in[1];   // int32 OR int64 — detected on device
    const float* W1 = (const float*)d_in[2];
    const float* b1 = (const float*)d_in[3];
    const float* W2 = (const float*)d_in[4];
    const float* b2 = (const float*)d_in[5];
    const float* Wl = (const float*)d_in[6];
    const float* bl = (const float*)d_in[7];
    float* out = (float*)d_out;

    // canonicalize + CSR build + norms (fused: 6 launches)
    detect_kernel<<<1, 256>>>(ei32);
    zero_cnt_kernel<<<NTILES, 256>>>();
    convert_hist_kernel<<<(N_EDGES + 255) / 256, 256>>>(ei32);
    scanA_kernel<<<NTILES, 256>>>();
    scanB_kernel<<<1, 512>>>();
    scanC_kernel<<<NTILES, 256>>>();
    fill_kernel<<<(N_EDGES + 255) / 256, 256>>>();

    // layer 1
    gemm_kernel<IN_DIM, 0><<<(N_NODES + 127) / 128, 256>>>(x, W1);
    gather_kernel<0><<<(N_NODES + 15) / 16, 256>>>(b1);

    // layer 2
    gemm_kernel<HID, 1><<<(N_NODES + 127) / 128, 256>>>(nullptr, W2);
    gather_kernel<1><<<(N_NODES + 15) / 16, 256>>>(b2);

    // classifier + log_softmax
    final_kernel<<<(N_NODES + 7) / 8, 256>>>(Wl, bl, out);
}

// round 8
// speedup vs baseline: 1.2248x; 1.2248x over previous
#include <cuda_runtime.h>
#include <math.h>

#define N_NODES 100000
#define N_EDGES 1600000
#define IN_DIM 128
#define HID 64
#define NTILES ((N_NODES + 255) / 256)   // 391

// ---------------- scratch (__device__ globals; referenced from DEVICE code only) ----------------
__device__ int d_is64;                         // 1 if edge_index delivered as int64
__device__ __align__(16) int d_src[N_EDGES];   // canonical int32 src
__device__ __align__(16) int d_dst[N_EDGES];   // canonical int32 dst
__device__ __align__(16) int d_cnt[N_NODES];
__device__ __align__(16) int d_rowptr[N_NODES + 1];
__device__ __align__(16) int d_bsum[512];
__device__ __align__(16) int d_boff[512];
__device__ __align__(16) int d_eidx[N_EDGES];
__device__ __align__(16) float d_dinv[N_NODES];
__device__ __align__(16) float d_g1[(size_t)N_NODES * HID];   // (x@W1)*dinv
__device__ __align__(16) float d_h1[(size_t)N_NODES * HID];   // relu(dinv*agg + b1)
__device__ __align__(16) float d_g2[(size_t)N_NODES * HID];   // (h1@W2)*dinv
__device__ __align__(16) float d_emb[(size_t)N_NODES * HID];  // dinv*agg + b2

// ---------------- dtype detection ----------------
__global__ void detect_kernel(const int* __restrict__ ei32) {
    __shared__ int any_nonzero;
    if (threadIdx.x == 0) any_nonzero = 0;
    __syncthreads();
    int local = 0;
    for (int i = threadIdx.x; i < 2048; i += blockDim.x)
        local |= ei32[2 * i + 1];
    if (local) atomicOr(&any_nonzero, 1);
    __syncthreads();
    if (threadIdx.x == 0) d_is64 = (any_nonzero == 0) ? 1 : 0;
}

__global__ void zero_cnt_kernel() {
    int i = blockIdx.x * blockDim.x + threadIdx.x;
    if (i < N_NODES) d_cnt[i] = 0;
}

// convert to canonical int32 + in-degree histogram, one pass
__global__ void convert_hist_kernel(const int* __restrict__ ei32) {
    int e = blockIdx.x * blockDim.x + threadIdx.x;
    if (e >= N_EDGES) return;
    int s, d;
    if (d_is64) {               // little-endian int64: low word holds the value
        s = ei32[2 * e];
        d = ei32[2 * (N_EDGES + e)];
    } else {
        s = ei32[e];
        d = ei32[N_EDGES + e];
    }
    s = min(max(s, 0), N_NODES - 1);   // clamp: no wild addresses downstream
    d = min(max(d, 0), N_NODES - 1);
    d_src[e] = s;
    d_dst[e] = d;
    atomicAdd(&d_cnt[d], 1);
}

// per-256-tile inclusive scan of degrees; also computes dinv and re-zeroes d_cnt
__global__ void scanA_kernel() {
    __shared__ int s[256];
    int t = threadIdx.x;
    int i = blockIdx.x * 256 + t;
    int v = (i < N_NODES) ? d_cnt[i] : 0;
    if (i < N_NODES) {
        d_dinv[i] = rsqrtf((float)v + 1.0f);  // +1 self-loop
        d_cnt[i] = 0;                          // reset for fill's atomic cursor
    }
    s[t] = v;
    __syncthreads();
#pragma unroll
    for (int off = 1; off < 256; off <<= 1) {
        int a = (t >= off) ? s[t - off] : 0;
        __syncthreads();
        s[t] += a;
        __syncthreads();
    }
    if (i < N_NODES) d_rowptr[i + 1] = s[t];
    if (t == 255) d_bsum[blockIdx.x] = s[255];
}

__global__ void scanB_kernel() {
    __shared__ int s[512];
    int t = threadIdx.x;
    int v = (t < NTILES) ? d_bsum[t] : 0;
    s[t] = v;
    __syncthreads();
#pragma unroll
    for (int off = 1; off < 512; off <<= 1) {
        int a = (t >= off) ? s[t - off] : 0;
        __syncthreads();
        s[t] += a;
        __syncthreads();
    }
    d_boff[t] = s[t] - v;  // exclusive
}

__global__ void scanC_kernel() {
    int i = blockIdx.x * 256 + threadIdx.x;
    if (i < N_NODES) d_rowptr[i + 1] += d_boff[blockIdx.x];
    if (i == 0) d_rowptr[0] = 0;
}

__global__ void fill_kernel() {
    int e = blockIdx.x * blockDim.x + threadIdx.x;
    if (e >= N_EDGES) return;
    int d = d_dst[e];
    int pos = d_rowptr[d] + atomicAdd(&d_cnt[d], 1);
    d_eidx[pos] = d_src[e];
}

// ---------------- tf32 tensor-core GEMM: out = (in @ W) * dinv ----------------
// Tile: 128 rows x 64 cols per block (8 warps, each warp 16x64).
// mma.m16n8k8.tf32; K in panels of 32. Padded smem (A stride 36, B stride 68):
// conflict-free fragment loads, 16B-aligned vector fills.
__device__ __forceinline__ unsigned f2tf32(float f) {
    unsigned u;
    asm("cvt.rna.tf32.f32 %0, %1;" : "=r"(u) : "f"(f));
    return u;
}

#define SA_STRIDE 36
#define SB_STRIDE 68

template <int KDIM, int LAYER>
__global__ __launch_bounds__(256) void gemm_kernel(const float* __restrict__ xin,
                                                   const float* __restrict__ W) {
    const float* in = (LAYER == 0) ? xin : d_h1;
    float* out = (LAYER == 0) ? d_g1 : d_g2;

    __shared__ unsigned sA[128 * SA_STRIDE];  // 18 KB
    __shared__ unsigned sB[32 * SB_STRIDE];   // 8.5 KB

    int tid = threadIdx.x;
    int w = tid >> 5;
    int lane = tid & 31;
    int gr = lane >> 2;   // group row 0..7
    int tg = lane & 3;    // thread-in-group 0..3
    int r0 = blockIdx.x * 128;
    int wrow = w * 16;    // warp's row offset within tile

    float c[8][4];
#pragma unroll
    for (int j = 0; j < 8; j++)
#pragma unroll
        for (int q = 0; q < 4; q++) c[j][q] = 0.0f;

#pragma unroll
    for (int kp = 0; kp < KDIM / 32; kp++) {
        // fill A panel: 128 rows x 32 cols, as 1024 float4 loads
#pragma unroll
        for (int it = 0; it < 4; it++) {
            int idx = tid + it * 256;
            int row = idx >> 3;
            int c4 = (idx & 7) * 4;
            float4 v = make_float4(0.f, 0.f, 0.f, 0.f);
            int grow = r0 + row;
            if (grow < N_NODES)
                v = *(const float4*)(in + (size_t)grow * KDIM + kp * 32 + c4);
            uint4 u = make_uint4(f2tf32(v.x), f2tf32(v.y), f2tf32(v.z), f2tf32(v.w));
            *(uint4*)(sA + row * SA_STRIDE + c4) = u;
        }
        // fill B panel: 32 rows x 64 cols, as 512 float4 loads
#pragma unroll
        for (int it = 0; it < 2; it++) {
            int idx = tid + it * 256;
            int row = idx >> 4;
            int c4 = (idx & 15) * 4;
            float4 v = *(const float4*)(W + (size_t)(kp * 32 + row) * 64 + c4);
            uint4 u = make_uint4(f2tf32(v.x), f2tf32(v.y), f2tf32(v.z), f2tf32(v.w));
            *(uint4*)(sB + row * SB_STRIDE + c4) = u;
        }
        __syncthreads();

#pragma unroll
        for (int kk = 0; kk < 32; kk += 8) {
            unsigned a0 = sA[(wrow + gr) * SA_STRIDE + kk + tg];
            unsigned a1 = sA[(wrow + gr + 8) * SA_STRIDE + kk + tg];
            unsigned a2 = sA[(wrow + gr) * SA_STRIDE + kk + tg + 4];
            unsigned a3 = sA[(wrow + gr + 8) * SA_STRIDE + kk + tg + 4];
#pragma unroll
            for (int j = 0; j < 8; j++) {
                unsigned b0 = sB[(kk + tg) * SB_STRIDE + j * 8 + gr];
                unsigned b1 = sB[(kk + tg + 4) * SB_STRIDE + j * 8 + gr];
                asm volatile(
                    "mma.sync.aligned.m16n8k8.row.col.f32.tf32.tf32.f32 "
                    "{%0,%1,%2,%3}, {%4,%5,%6,%7}, {%8,%9}, {%0,%1,%2,%3};"
                    : "+f"(c[j][0]), "+f"(c[j][1]), "+f"(c[j][2]), "+f"(c[j][3])
                    : "r"(a0), "r"(a1), "r"(a2), "r"(a3), "r"(b0), "r"(b1));
            }
        }
        __syncthreads();
    }

    // epilogue: row_lo = r0 + wrow + gr, row_hi = +8; cols j*8 + 2*tg (+1)
    int row_lo = r0 + wrow + gr;
    int row_hi = row_lo + 8;
    float dv_lo = (row_lo < N_NODES) ? d_dinv[row_lo] : 0.f;
    float dv_hi = (row_hi < N_NODES) ? d_dinv[row_hi] : 0.f;
#pragma unroll
    for (int j = 0; j < 8; j++) {
        int col = j * 8 + 2 * tg;
        if (row_lo < N_NODES) {
            float2 o = make_float2(c[j][0] * dv_lo, c[j][1] * dv_lo);
            *(float2*)(out + (size_t)row_lo * HID + col) = o;
        }
        if (row_hi < N_NODES) {
            float2 o = make_float2(c[j][2] * dv_hi, c[j][3] * dv_hi);
            *(float2*)(out + (size_t)row_hi * HID + col) = o;
        }
    }
}

// ---------------- gather-aggregate: out[n] = post(dinv[n]*(g[n] + sum g[src]) + bias) ----------
// 16 threads per node, each owns one float4 lane; 4-edge unroll (R4 known-good config).
template <int LAYER>
__global__ __launch_bounds__(256) void gather_kernel(const float* __restrict__ bias) {
    const float* g = (LAYER == 0) ? d_g1 : d_g2;
    float* out = (LAYER == 0) ? d_h1 : d_emb;

    int t = threadIdx.x;
    int node = blockIdx.x * 16 + (t >> 4);
    if (node >= N_NODES) return;
    int lane = t & 15;

    int base = d_rowptr[node];
    int end  = d_rowptr[node + 1];

    float4 a0 = *(const float4*)(g + (size_t)node * HID + lane * 4);  // self-loop
    float4 a1 = make_float4(0.f, 0.f, 0.f, 0.f);
    float4 a2 = make_float4(0.f, 0.f, 0.f, 0.f);
    float4 a3 = make_float4(0.f, 0.f, 0.f, 0.f);

    int i = base;
    for (; i + 4 <= end; i += 4) {
        int s0 = d_eidx[i + 0];
        int s1 = d_eidx[i + 1];
        int s2 = d_eidx[i + 2];
        int s3 = d_eidx[i + 3];
        float4 v0 = *(const float4*)(g + (size_t)s0 * HID + lane * 4);
        float4 v1 = *(const float4*)(g + (size_t)s1 * HID + lane * 4);
        float4 v2 = *(const float4*)(g + (size_t)s2 * HID + lane * 4);
        float4 v3 = *(const float4*)(g + (size_t)s3 * HID + lane * 4);
        a0.x += v0.x; a0.y += v0.y; a0.z += v0.z; a0.w += v0.w;
        a1.x += v1.x; a1.y += v1.y; a1.z += v1.z; a1.w += v1.w;
        a2.x += v2.x; a2.y += v2.y; a2.z += v2.z; a2.w += v2.w;
        a3.x += v3.x; a3.y += v3.y; a3.z += v3.z; a3.w += v3.w;
    }
    for (; i < end; i++) {
        int s = d_eidx[i];
        float4 v = *(const float4*)(g + (size_t)s * HID + lane * 4);
        a0.x += v.x; a0.y += v.y; a0.z += v.z; a0.w += v.w;
    }
    float4 sum = make_float4(a0.x + a1.x + a2.x + a3.x,
                             a0.y + a1.y + a2.y + a3.y,
                             a0.z + a1.z + a2.z + a3.z,
                             a0.w + a1.w + a2.w + a3.w);
    float dv = d_dinv[node];
    float4 bb = *(const float4*)(bias + lane * 4);
    float4 o;
    o.x = fmaf(dv, sum.x, bb.x);
    o.y = fmaf(dv, sum.y, bb.y);
    o.z = fmaf(dv, sum.z, bb.z);
    o.w = fmaf(dv, sum.w, bb.w);
    if (LAYER == 0) {
        o.x = fmaxf(o.x, 0.f); o.y = fmaxf(o.y, 0.f);
        o.z = fmaxf(o.z, 0.f); o.w = fmaxf(o.w, 0.f);
    }
    *(float4*)(out + (size_t)node * HID + lane * 4) = o;
}

// ---------------- final: logits = emb@Wl + bl; log_softmax. one warp/node ----------------
__global__ __launch_bounds__(256) void final_kernel(const float* __restrict__ Wl,
                                                    const float* __restrict__ bl,
                                                    float* __restrict__ out) {
    __shared__ float sWl[64 * 40];
    __shared__ float sbl[40];
    __shared__ float semb[8][64];
    int tid = threadIdx.x;
    for (int i = tid; i < 64 * 40; i += 256) sWl[i] = Wl[i];
    if (tid < 40) sbl[tid] = bl[tid];
    __syncthreads();

    int w = tid >> 5, lane = tid & 31;
    int n = blockIdx.x * 8 + w;
    if (n >= N_NODES) return;

    float e0 = d_emb[(size_t)n * HID + lane];
    float e1 = d_emb[(size_t)n * HID + 32 + lane];
    semb[w][lane] = e0;
    semb[w][32 + lane] = e1;
    __syncwarp();

    float v0 = sbl[lane];
    float v1 = (lane < 8) ? sbl[32 + lane] : -INFINITY;
#pragma unroll 8
    for (int k = 0; k < 64; k++) {
        float ev = semb[w][k];
        v0 = fmaf(ev, sWl[k * 40 + lane], v0);
        if (lane < 8) v1 = fmaf(ev, sWl[k * 40 + 32 + lane], v1);
    }
    float m = fmaxf(v0, v1);
#pragma unroll
    for (int o = 16; o; o >>= 1) m = fmaxf(m, __shfl_xor_sync(0xffffffffu, m, o));
    float s = expf(v0 - m) + ((lane < 8) ? expf(v1 - m) : 0.0f);
#pragma unroll
    for (int o = 16; o; o >>= 1) s += __shfl_xor_sync(0xffffffffu, s, o);
    float lse = m + logf(s);

    out[(size_t)n * 40 + lane] = v0 - lse;
    if (lane < 8) out[(size_t)n * 40 + 32 + lane] = v1 - lse;
}

extern "C" void kernel_launch(void* const* d_in, const int* in_sizes, int n_in,
                              void* d_out, int out_size) {
    const float* x = (const float*)d_in[0];
    const int* ei32 = (const int*)d_in[1];   // int32 OR int64 — detected on device
    const float* W1 = (const float*)d_in[2];
    const float* b1 = (const float*)d_in[3];
    const float* W2 = (const float*)d_in[4];
    const float* b2 = (const float*)d_in[5];
    const float* Wl = (const float*)d_in[6];
    const float* bl = (const float*)d_in[7];
    float* out = (float*)d_out;

    // canonicalize + CSR build + norms
    detect_kernel<<<1, 256>>>(ei32);
    zero_cnt_kernel<<<NTILES, 256>>>();
    convert_hist_kernel<<<(N_EDGES + 255) / 256, 256>>>(ei32);
    scanA_kernel<<<NTILES, 256>>>();
    scanB_kernel<<<1, 512>>>();
    scanC_kernel<<<NTILES, 256>>>();
    fill_kernel<<<(N_EDGES + 255) / 256, 256>>>();

    // layer 1
    gemm_kernel<IN_DIM, 0><<<(N_NODES + 127) / 128, 256>>>(x, W1);
    gather_kernel<0><<<(N_NODES + 15) / 16, 256>>>(b1);

    // layer 2
    gemm_kernel<HID, 1><<<(N_NODES + 127) / 128, 256>>>(nullptr, W2);
    gather_kernel<1><<<(N_NODES + 15) / 16, 256>>>(b2);

    // classifier + log_softmax
    final_kernel<<<(N_NODES + 7) / 8, 256>>>(Wl, bl, out);
}